// round 2
// baseline (speedup 1.0000x reference)
#include <cuda_runtime.h>
#include <math.h>

#define S 2048
#define B 32
#define D 1024
#define NCHUNK 32
#define CHUNK (S / NCHUNK)   // 64
#define KSPLIT 8
#define KT 64

// Static scratch (no allocations allowed)
__device__ float g_semi[B * D];                    // 128 KB
__device__ float g_pm[B * NCHUNK];
__device__ float g_pl[B * NCHUNK];
__device__ float g_pacc[(size_t)B * NCHUNK * D];   // 4 MB
__device__ float g_xcat[B * 2 * D];                // 256 KB  (concat(s_tilde, h))
__device__ float g_p3[(size_t)KSPLIT * B * D];     // 1 MB

// ---------------------------------------------------------------------------
// K0: semi[b][d] = sum_k h[b][k] * Wi[d][k]     (grid = D blocks, 256 thr)
// ---------------------------------------------------------------------------
__global__ void k0_semi(const float* __restrict__ h, const float* __restrict__ Wi) {
    __shared__ float wrow[D];
    int d = blockIdx.x;
    const float* wr = Wi + (size_t)d * D;
    for (int i = threadIdx.x; i < D; i += 256) wrow[i] = wr[i];
    __syncthreads();
    int warp = threadIdx.x >> 5, lane = threadIdx.x & 31;
    for (int b = warp; b < B; b += 8) {
        const float* hb = h + b * D;
        float s = 0.f;
        for (int k = lane; k < D; k += 32) s += hb[k] * wrow[k];
        #pragma unroll
        for (int o = 16; o; o >>= 1) s += __shfl_xor_sync(0xffffffffu, s, o);
        if (lane == 0) g_semi[b * D + d] = s;
    }
}

// ---------------------------------------------------------------------------
// K1: fused logits + online softmax + weighted accumulation (one HBM pass)
// grid = (NCHUNK, B), 256 threads, each thread owns 4 consecutive d (float4)
// ---------------------------------------------------------------------------
__global__ void k1_online(const float* __restrict__ input) {
    int c = blockIdx.x;
    int b = blockIdx.y;
    int t = threadIdx.x;
    int warp = t >> 5, lane = t & 31;

    const float4* semi4 = (const float4*)(g_semi + b * D);
    float4 sem = semi4[t];

    float4 acc = make_float4(0.f, 0.f, 0.f, 0.f);
    float m = -INFINITY, l = 0.f;

    __shared__ float red[2][8];

    int s0 = c * CHUNK;
    for (int i = 0; i < CHUNK; ++i) {
        int s = s0 + i;
        const float4* row = (const float4*)(input + ((size_t)s * B + b) * D);
        float4 x = row[t];
        float p = x.x * sem.x + x.y * sem.y + x.z * sem.z + x.w * sem.w;
        #pragma unroll
        for (int o = 16; o; o >>= 1) p += __shfl_xor_sync(0xffffffffu, p, o);
        int buf = i & 1;
        if (lane == 0) red[buf][warp] = p;
        __syncthreads();
        float logit = red[buf][0] + red[buf][1] + red[buf][2] + red[buf][3]
                    + red[buf][4] + red[buf][5] + red[buf][6] + red[buf][7];
        if (logit > m) {
            float sc = __expf(m - logit);   // exp(-inf)=0 handles first iter
            acc.x *= sc; acc.y *= sc; acc.z *= sc; acc.w *= sc;
            l *= sc;
            m = logit;
        }
        float w = __expf(logit - m);
        l += w;
        acc.x += w * x.x; acc.y += w * x.y; acc.z += w * x.z; acc.w += w * x.w;
    }

    float4* pa = (float4*)(g_pacc + (size_t)(b * NCHUNK + c) * D);
    pa[t] = acc;
    if (t == 0) {
        g_pm[b * NCHUNK + c] = m;
        g_pl[b * NCHUNK + c] = l;
    }
}

// ---------------------------------------------------------------------------
// K2: combine chunk partials -> s_tilde, build xcat = [s_tilde | h]
// grid = B, 256 threads
// ---------------------------------------------------------------------------
__global__ void k2_combine(const float* __restrict__ h) {
    int b = blockIdx.x;
    int t = threadIdx.x;

    float M = -INFINITY;
    #pragma unroll
    for (int c = 0; c < NCHUNK; c++) M = fmaxf(M, g_pm[b * NCHUNK + c]);

    float f[NCHUNK];
    float L = 0.f;
    #pragma unroll
    for (int c = 0; c < NCHUNK; c++) {
        float e = __expf(g_pm[b * NCHUNK + c] - M);
        f[c] = e;
        L += g_pl[b * NCHUNK + c] * e;
    }
    float invL = 1.f / L;

    float4 s = make_float4(0.f, 0.f, 0.f, 0.f);
    #pragma unroll
    for (int c = 0; c < NCHUNK; c++) {
        const float4* pa = (const float4*)(g_pacc + (size_t)(b * NCHUNK + c) * D);
        float4 a = pa[t];
        float e = f[c];
        s.x += a.x * e; s.y += a.y * e; s.z += a.z * e; s.w += a.w * e;
    }
    s.x *= invL; s.y *= invL; s.z *= invL; s.w *= invL;

    float4* xc = (float4*)(g_xcat + (size_t)b * 2 * D);
    xc[t] = s;
    const float4* hb = (const float4*)(h + (size_t)b * D);
    xc[256 + t] = hb[t];
}

// ---------------------------------------------------------------------------
// K3: partial GEMM  p3[ks][b][j] = sum_{k in split} xcat[b][k] * Wo[j][k]
// grid = (16 j-tiles, KSPLIT), 256 threads, each thread 2b x 4j
// ---------------------------------------------------------------------------
__global__ void k3_gemm(const float* __restrict__ Wo) {
    int jt = blockIdx.x;         // 0..15   -> 64 j per tile
    int ks = blockIdx.y;         // 0..7    -> 256 k per split
    int j0 = jt * 64;
    int k0 = ks * 256;

    __shared__ float Xs[32][KT + 1];
    __shared__ float Ws[64][KT + 1];

    int t = threadIdx.x;
    int tb = t & 15;             // 16 along b, 2 rows each
    int tj = t >> 4;             // 16 along j, 4 cols each

    float acc[2][4] = {{0.f,0.f,0.f,0.f},{0.f,0.f,0.f,0.f}};

    for (int kt = 0; kt < 256; kt += KT) {
        for (int i = t; i < 32 * KT; i += 256) {
            int r = i / KT, cc = i % KT;
            Xs[r][cc] = g_xcat[(size_t)r * 2048 + k0 + kt + cc];
        }
        for (int i = t; i < 64 * KT; i += 256) {
            int r = i / KT, cc = i % KT;
            Ws[r][cc] = Wo[(size_t)(j0 + r) * 2048 + k0 + kt + cc];
        }
        __syncthreads();
        #pragma unroll 8
        for (int k = 0; k < KT; k++) {
            float x0 = Xs[2 * tb][k];
            float x1 = Xs[2 * tb + 1][k];
            float w0 = Ws[4 * tj + 0][k];
            float w1 = Ws[4 * tj + 1][k];
            float w2 = Ws[4 * tj + 2][k];
            float w3 = Ws[4 * tj + 3][k];
            acc[0][0] += x0 * w0; acc[0][1] += x0 * w1;
            acc[0][2] += x0 * w2; acc[0][3] += x0 * w3;
            acc[1][0] += x1 * w0; acc[1][1] += x1 * w1;
            acc[1][2] += x1 * w2; acc[1][3] += x1 * w3;
        }
        __syncthreads();
    }

    #pragma unroll
    for (int i = 0; i < 2; i++)
        #pragma unroll
        for (int q = 0; q < 4; q++)
            g_p3[((size_t)ks * B + (2 * tb + i)) * D + j0 + 4 * tj + q] = acc[i][q];
}

// ---------------------------------------------------------------------------
// K4: reduce split-K partials + tanh -> output [B, D]
// ---------------------------------------------------------------------------
__global__ void k4_out(float* __restrict__ out) {
    int i = blockIdx.x * 256 + threadIdx.x;   // 0..32767
    float s = 0.f;
    #pragma unroll
    for (int ks = 0; ks < KSPLIT; ks++) s += g_p3[(size_t)ks * B * D + i];
    out[i] = tanhf(s);
}

// ---------------------------------------------------------------------------
extern "C" void kernel_launch(void* const* d_in, const int* in_sizes, int n_in,
                              void* d_out, int out_size) {
    const float* input = (const float*)d_in[0];   // [S, B, D]
    const float* h     = (const float*)d_in[1];   // [B, D]
    const float* Wi    = (const float*)d_in[2];   // [D, D]
    const float* Wo    = (const float*)d_in[3];   // [D, 2D]
    float* out         = (float*)d_out;           // [B, D]

    k0_semi<<<D, 256>>>(h, Wi);
    k1_online<<<dim3(NCHUNK, B), 256>>>(input);
    k2_combine<<<B, 256>>>(h);
    k3_gemm<<<dim3(16, KSPLIT), 256>>>(Wo);
    k4_out<<<(B * D) / 256, 256>>>(out);
}

// round 6
// speedup vs baseline: 1.0411x; 1.0411x over previous
#include <cuda_runtime.h>
#include <math.h>

#define S 2048
#define B 32
#define D 1024
#define NCHUNK 32
#define CHUNK (S / NCHUNK)   // 64
#define KT 64
#define KS0 16               // k-splits for semi GEMM   (k=1024 -> 16 x 64)
#define KS3 32               // k-splits for output GEMM (k=2048 -> 32 x 64)

// Static scratch (no allocations allowed). NEVER passed as host-side kernel
// args — always referenced from device code (host-side __device__ symbol
// decay gives an invalid pointer; that was the R4/R5 bug).
__device__ float g_semi[B * D];                    // 128 KB
__device__ float g_p0[(size_t)KS0 * B * D];        // 2 MB
__device__ float g_pm[B * NCHUNK];
__device__ float g_pl[B * NCHUNK];
__device__ float g_pacc[(size_t)B * NCHUNK * D];   // 4 MB
__device__ float g_xcat[B * 2 * D];                // 256 KB (concat(s_tilde, h))
__device__ float g_p3[(size_t)KS3 * B * D];        // 4 MB

// ---------------------------------------------------------------------------
// Shared partial-GEMM body (R2 k3_gemm tile, one 64-k slice per block):
//   P[ks][r][j0..j0+63] = sum_{k in [ks*64,(ks+1)*64)} A[r][k] * W[j][k]
// 256 threads, 2x4 outputs per thread. Pointers are resolved in DEVICE code.
// ---------------------------------------------------------------------------
__device__ __forceinline__ void gemm_body(
    const float* __restrict__ A, const float* __restrict__ W,
    float* __restrict__ P, int astride, int wstride)
{
    int jt = blockIdx.x;         // 0..15 -> 64 j per tile
    int ks = blockIdx.y;
    int j0 = jt * 64;
    int k0 = ks * KT;

    __shared__ float Xs[32][KT + 1];
    __shared__ float Ws[64][KT + 1];

    int t = threadIdx.x;
    int tb = t & 15;             // 16 along b, 2 rows each
    int tj = t >> 4;             // 16 along j, 4 cols each

    for (int i = t; i < 32 * KT; i += 256) {
        int r = i / KT, cc = i % KT;
        Xs[r][cc] = A[(size_t)r * astride + k0 + cc];
    }
    for (int i = t; i < 64 * KT; i += 256) {
        int r = i / KT, cc = i % KT;
        Ws[r][cc] = W[(size_t)(j0 + r) * wstride + k0 + cc];
    }
    __syncthreads();

    float acc[2][4] = {{0.f,0.f,0.f,0.f},{0.f,0.f,0.f,0.f}};
    #pragma unroll 8
    for (int k = 0; k < KT; k++) {
        float x0 = Xs[2 * tb][k];
        float x1 = Xs[2 * tb + 1][k];
        float w0 = Ws[4 * tj + 0][k];
        float w1 = Ws[4 * tj + 1][k];
        float w2 = Ws[4 * tj + 2][k];
        float w3 = Ws[4 * tj + 3][k];
        acc[0][0] += x0 * w0; acc[0][1] += x0 * w1;
        acc[0][2] += x0 * w2; acc[0][3] += x0 * w3;
        acc[1][0] += x1 * w0; acc[1][1] += x1 * w1;
        acc[1][2] += x1 * w2; acc[1][3] += x1 * w3;
    }

    #pragma unroll
    for (int i = 0; i < 2; i++)
        #pragma unroll
        for (int q = 0; q < 4; q++)
            P[((size_t)ks * B + (2 * tb + i)) * D + j0 + 4 * tj + q] = acc[i][q];
}

// semi partials: A = h [32,1024], W = Wi [1024,1024] -> g_p0
__global__ void __launch_bounds__(256) g0_semi_part(
    const float* __restrict__ h, const float* __restrict__ Wi)
{
    gemm_body(h, Wi, g_p0, D, D);
}

// output partials: A = g_xcat [32,2048], W = Wo [1024,2048] -> g_p3
__global__ void __launch_bounds__(256) g3_out_part(const float* __restrict__ Wo)
{
    gemm_body(g_xcat, Wo, g_p3, 2 * D, 2 * D);
}

// ---------------------------------------------------------------------------
// k0b: g_semi = sum over KS0 partials
// ---------------------------------------------------------------------------
__global__ void __launch_bounds__(256) k0b_sum() {
    int i = blockIdx.x * 256 + threadIdx.x;   // 0..32767
    float s = 0.f;
    #pragma unroll
    for (int ks = 0; ks < KS0; ks++) s += g_p0[(size_t)ks * B * D + i];
    g_semi[i] = s;
}

// ---------------------------------------------------------------------------
// K1: fused logits + online softmax + weighted accumulation (one HBM pass)
// grid = (NCHUNK, B), 256 threads, each thread owns 4 consecutive d (float4).
// R2-proven body + software-pipelined row prefetch.
// ---------------------------------------------------------------------------
__global__ void k1_online(const float* __restrict__ input) {
    int c = blockIdx.x;
    int b = blockIdx.y;
    int t = threadIdx.x;
    int warp = t >> 5, lane = t & 31;

    const float4* semi4 = (const float4*)(g_semi + b * D);
    float4 sem = semi4[t];

    float4 acc = make_float4(0.f, 0.f, 0.f, 0.f);
    float m = -INFINITY, l = 0.f;

    __shared__ float red[2][8];

    const size_t rowstride4 = (size_t)B * D / 4;    // float4 stride between s
    const float4* row0 = (const float4*)(input + ((size_t)(c * CHUNK) * B + b) * D) + t;

    float4 x = *row0;
    for (int i = 0; i < CHUNK; ++i) {
        float4 xn = x;
        if (i + 1 < CHUNK) xn = row0[(size_t)(i + 1) * rowstride4];   // prefetch
        float p = x.x * sem.x + x.y * sem.y + x.z * sem.z + x.w * sem.w;
        #pragma unroll
        for (int o = 16; o; o >>= 1) p += __shfl_xor_sync(0xffffffffu, p, o);
        int buf = i & 1;
        if (lane == 0) red[buf][warp] = p;
        __syncthreads();
        float logit = red[buf][0] + red[buf][1] + red[buf][2] + red[buf][3]
                    + red[buf][4] + red[buf][5] + red[buf][6] + red[buf][7];
        if (logit > m) {
            float sc = __expf(m - logit);   // exp(-inf)=0 handles first iter
            acc.x *= sc; acc.y *= sc; acc.z *= sc; acc.w *= sc;
            l *= sc;
            m = logit;
        }
        float w = __expf(logit - m);
        l += w;
        acc.x += w * x.x; acc.y += w * x.y; acc.z += w * x.z; acc.w += w * x.w;
        x = xn;
    }

    float4* pa = (float4*)(g_pacc + (size_t)(b * NCHUNK + c) * D);
    pa[t] = acc;
    if (t == 0) {
        g_pm[b * NCHUNK + c] = m;
        g_pl[b * NCHUNK + c] = l;
    }
}

// ---------------------------------------------------------------------------
// K2: combine chunk partials -> s_tilde, build xcat = [s_tilde | h]
// grid = B, 256 threads
// ---------------------------------------------------------------------------
__global__ void k2_combine(const float* __restrict__ h) {
    int b = blockIdx.x;
    int t = threadIdx.x;

    float M = -INFINITY;
    #pragma unroll
    for (int c = 0; c < NCHUNK; c++) M = fmaxf(M, g_pm[b * NCHUNK + c]);

    float f[NCHUNK];
    float L = 0.f;
    #pragma unroll
    for (int c = 0; c < NCHUNK; c++) {
        float e = __expf(g_pm[b * NCHUNK + c] - M);
        f[c] = e;
        L += g_pl[b * NCHUNK + c] * e;
    }
    float invL = 1.f / L;

    float4 s = make_float4(0.f, 0.f, 0.f, 0.f);
    #pragma unroll
    for (int c = 0; c < NCHUNK; c++) {
        const float4* pa = (const float4*)(g_pacc + (size_t)(b * NCHUNK + c) * D);
        float4 a = pa[t];
        float e = f[c];
        s.x += a.x * e; s.y += a.y * e; s.z += a.z * e; s.w += a.w * e;
    }
    s.x *= invL; s.y *= invL; s.z *= invL; s.w *= invL;

    float4* xc = (float4*)(g_xcat + (size_t)b * 2 * D);
    xc[t] = s;
    const float4* hb = (const float4*)(h + (size_t)b * D);
    xc[256 + t] = hb[t];
}

// ---------------------------------------------------------------------------
// K4: reduce split-K partials + tanh -> output [B, D]
// ---------------------------------------------------------------------------
__global__ void __launch_bounds__(256) k4_out(float* __restrict__ out) {
    int i = blockIdx.x * 256 + threadIdx.x;   // 0..32767
    float s = 0.f;
    #pragma unroll
    for (int ks = 0; ks < KS3; ks++) s += g_p3[(size_t)ks * B * D + i];
    out[i] = tanhf(s);
}

// ---------------------------------------------------------------------------
extern "C" void kernel_launch(void* const* d_in, const int* in_sizes, int n_in,
                              void* d_out, int out_size) {
    const float* input = (const float*)d_in[0];   // [S, B, D]
    const float* h     = (const float*)d_in[1];   // [B, D]
    const float* Wi    = (const float*)d_in[2];   // [D, D]
    const float* Wo    = (const float*)d_in[3];   // [D, 2D]
    float* out         = (float*)d_out;           // [B, D]

    g0_semi_part<<<dim3(16, KS0), 256>>>(h, Wi);  // semi partials
    k0b_sum<<<(B * D) / 256, 256>>>();            // g_semi = sum partials
    k1_online<<<dim3(NCHUNK, B), 256>>>(input);   // fused streaming pass
    k2_combine<<<B, 256>>>(h);                    // s_tilde | h
    g3_out_part<<<dim3(16, KS3), 256>>>(Wo);      // output GEMM partials
    k4_out<<<(B * D) / 256, 256>>>(out);          // reduce + tanh
}

// round 7
// speedup vs baseline: 1.1954x; 1.1482x over previous
#include <cuda_runtime.h>
#include <math.h>

#define S 2048
#define B 32
#define D 1024
#define NCHUNK 32
#define CHUNK (S / NCHUNK)   // 64
#define RPW 8                // rows per warp in k1 (8 warps * 8 = 64 = CHUNK)
#define KT 64
#define KS0 16               // k-splits for semi GEMM   (k=1024 -> 16 x 64)
#define KS3 32               // k-splits for output GEMM (k=2048 -> 32 x 64)

// Static scratch (no allocations allowed). NEVER passed as host-side kernel
// args — always referenced from device code (host-side __device__ symbol
// decay gives an invalid pointer; that was the R4/R5 bug).
__device__ float g_semi[B * D];                    // 128 KB
__device__ float g_p0[(size_t)KS0 * B * D];        // 2 MB
__device__ float g_pm[B * NCHUNK];
__device__ float g_pl[B * NCHUNK];
__device__ float g_pacc[(size_t)B * NCHUNK * D];   // 4 MB
__device__ float g_xcat[B * 2 * D];                // 256 KB (concat(s_tilde, h))
__device__ float g_p3[(size_t)KS3 * B * D];        // 4 MB

// ---------------------------------------------------------------------------
// Shared partial-GEMM body (proven in R2/R6):
//   P[ks][r][j0..j0+63] = sum_{k in [ks*64,(ks+1)*64)} A[r][k] * W[j][k]
// 256 threads, 2x4 outputs per thread. Pointers resolved in DEVICE code.
// ---------------------------------------------------------------------------
__device__ __forceinline__ void gemm_body(
    const float* __restrict__ A, const float* __restrict__ W,
    float* __restrict__ P, int astride, int wstride)
{
    int jt = blockIdx.x;         // 0..15 -> 64 j per tile
    int ks = blockIdx.y;
    int j0 = jt * 64;
    int k0 = ks * KT;

    __shared__ float Xs[32][KT + 1];
    __shared__ float Ws[64][KT + 1];

    int t = threadIdx.x;
    int tb = t & 15;             // 16 along b, 2 rows each
    int tj = t >> 4;             // 16 along j, 4 cols each

    for (int i = t; i < 32 * KT; i += 256) {
        int r = i / KT, cc = i % KT;
        Xs[r][cc] = A[(size_t)r * astride + k0 + cc];
    }
    for (int i = t; i < 64 * KT; i += 256) {
        int r = i / KT, cc = i % KT;
        Ws[r][cc] = W[(size_t)(j0 + r) * wstride + k0 + cc];
    }
    __syncthreads();

    float acc[2][4] = {{0.f,0.f,0.f,0.f},{0.f,0.f,0.f,0.f}};
    #pragma unroll 8
    for (int k = 0; k < KT; k++) {
        float x0 = Xs[2 * tb][k];
        float x1 = Xs[2 * tb + 1][k];
        float w0 = Ws[4 * tj + 0][k];
        float w1 = Ws[4 * tj + 1][k];
        float w2 = Ws[4 * tj + 2][k];
        float w3 = Ws[4 * tj + 3][k];
        acc[0][0] += x0 * w0; acc[0][1] += x0 * w1;
        acc[0][2] += x0 * w2; acc[0][3] += x0 * w3;
        acc[1][0] += x1 * w0; acc[1][1] += x1 * w1;
        acc[1][2] += x1 * w2; acc[1][3] += x1 * w3;
    }

    #pragma unroll
    for (int i = 0; i < 2; i++)
        #pragma unroll
        for (int q = 0; q < 4; q++)
            P[((size_t)ks * B + (2 * tb + i)) * D + j0 + 4 * tj + q] = acc[i][q];
}

// semi partials: A = h [32,1024], W = Wi [1024,1024] -> g_p0
__global__ void __launch_bounds__(256) g0_semi_part(
    const float* __restrict__ h, const float* __restrict__ Wi)
{
    gemm_body(h, Wi, g_p0, D, D);
}

// output partials: A = g_xcat [32,2048], W = Wo [1024,2048] -> g_p3
__global__ void __launch_bounds__(256) g3_out_part(const float* __restrict__ Wo)
{
    gemm_body(g_xcat, Wo, g_p3, 2 * D, 2 * D);
}

// ---------------------------------------------------------------------------
// k0b: g_semi = sum over KS0 partials
// ---------------------------------------------------------------------------
__global__ void __launch_bounds__(256) k0b_sum() {
    int i = blockIdx.x * 256 + threadIdx.x;   // 0..32767
    float s = 0.f;
    #pragma unroll
    for (int ks = 0; ks < KS0; ks++) s += g_p0[(size_t)ks * B * D + i];
    g_semi[i] = s;
}

// ---------------------------------------------------------------------------
// K1: fused logits + online softmax + weighted accumulation, one HBM pass.
// grid = (NCHUNK, B), 256 thr. Each WARP spans full D (8 float4/lane) and
// owns RPW=8 rows — no block sync in the hot loop. Block merge at the end.
// ---------------------------------------------------------------------------
__global__ void __launch_bounds__(256, 2) k1_online(const float* __restrict__ input) {
    int c = blockIdx.x, b = blockIdx.y;
    int t = threadIdx.x, warp = t >> 5, lane = t & 31;

    float4 sem[8];
    const float4* semi4 = (const float4*)(g_semi + b * D);
    #pragma unroll
    for (int j = 0; j < 8; j++) sem[j] = semi4[lane + 32 * j];

    float4 acc[8];
    #pragma unroll
    for (int j = 0; j < 8; j++) acc[j] = make_float4(0.f, 0.f, 0.f, 0.f);
    float m = -INFINITY, l = 0.f;

    int s0 = c * CHUNK + warp * RPW;
    for (int i = 0; i < RPW; i++) {
        const float4* row = (const float4*)(input + ((size_t)(s0 + i) * B + b) * D);
        float4 x[8];
        #pragma unroll
        for (int j = 0; j < 8; j++) x[j] = row[lane + 32 * j];
        float p = 0.f;
        #pragma unroll
        for (int j = 0; j < 8; j++)
            p += x[j].x * sem[j].x + x[j].y * sem[j].y
               + x[j].z * sem[j].z + x[j].w * sem[j].w;
        #pragma unroll
        for (int o = 16; o; o >>= 1) p += __shfl_xor_sync(0xffffffffu, p, o);
        if (p > m) {
            float sc = __expf(m - p);          // exp(-inf)=0 handles first row
            #pragma unroll
            for (int j = 0; j < 8; j++) {
                acc[j].x *= sc; acc[j].y *= sc; acc[j].z *= sc; acc[j].w *= sc;
            }
            l *= sc; m = p;
        }
        float w = __expf(p - m);
        l += w;
        #pragma unroll
        for (int j = 0; j < 8; j++) {
            acc[j].x += w * x[j].x; acc[j].y += w * x[j].y;
            acc[j].z += w * x[j].z; acc[j].w += w * x[j].w;
        }
    }

    // merge 8 warps (each covers the full D range)
    __shared__ float sm[8], sl[8];
    __shared__ float4 sacc[8][256];            // 32 KB
    if (lane == 0) { sm[warp] = m; sl[warp] = l; }
    __syncthreads();
    float M = -INFINITY;
    #pragma unroll
    for (int w = 0; w < 8; w++) M = fmaxf(M, sm[w]);
    float L = 0.f;
    #pragma unroll
    for (int w = 0; w < 8; w++) L += sl[w] * __expf(sm[w] - M);
    float f = __expf(m - M);
    #pragma unroll
    for (int j = 0; j < 8; j++) {
        float4 a = acc[j];
        a.x *= f; a.y *= f; a.z *= f; a.w *= f;
        sacc[warp][lane + 32 * j] = a;
    }
    __syncthreads();
    float4 s = make_float4(0.f, 0.f, 0.f, 0.f);
    #pragma unroll
    for (int w = 0; w < 8; w++) {
        float4 a = sacc[w][t];
        s.x += a.x; s.y += a.y; s.z += a.z; s.w += a.w;
    }
    ((float4*)(g_pacc + (size_t)(b * NCHUNK + c) * D))[t] = s;
    if (t == 0) { g_pm[b * NCHUNK + c] = M; g_pl[b * NCHUNK + c] = L; }
}

// ---------------------------------------------------------------------------
// K2: combine chunk partials -> s_tilde, build xcat = [s_tilde | h]
// grid = (8 d-slices, B), 128 threads
// ---------------------------------------------------------------------------
__global__ void __launch_bounds__(128) k2_combine(const float* __restrict__ h) {
    int b = blockIdx.y;
    int d = blockIdx.x * 128 + threadIdx.x;

    float M = -INFINITY;
    #pragma unroll
    for (int c = 0; c < NCHUNK; c++) M = fmaxf(M, g_pm[b * NCHUNK + c]);
    float fv[NCHUNK];
    float L = 0.f;
    #pragma unroll
    for (int c = 0; c < NCHUNK; c++) {
        float e = __expf(g_pm[b * NCHUNK + c] - M);
        fv[c] = e;
        L += g_pl[b * NCHUNK + c] * e;
    }
    float invL = 1.f / L;

    float s = 0.f;
    #pragma unroll
    for (int c = 0; c < NCHUNK; c++)
        s += g_pacc[(size_t)(b * NCHUNK + c) * D + d] * fv[c];

    g_xcat[(size_t)b * 2 * D + d]     = s * invL;
    g_xcat[(size_t)b * 2 * D + D + d] = h[(size_t)b * D + d];
}

// ---------------------------------------------------------------------------
// K4: reduce split-K partials + tanh -> output [B, D]
// ---------------------------------------------------------------------------
__global__ void __launch_bounds__(256) k4_out(float* __restrict__ out) {
    int i = blockIdx.x * 256 + threadIdx.x;   // 0..32767
    float s = 0.f;
    #pragma unroll
    for (int ks = 0; ks < KS3; ks++) s += g_p3[(size_t)ks * B * D + i];
    out[i] = tanhf(s);
}

// ---------------------------------------------------------------------------
extern "C" void kernel_launch(void* const* d_in, const int* in_sizes, int n_in,
                              void* d_out, int out_size) {
    const float* input = (const float*)d_in[0];   // [S, B, D]
    const float* h     = (const float*)d_in[1];   // [B, D]
    const float* Wi    = (const float*)d_in[2];   // [D, D]
    const float* Wo    = (const float*)d_in[3];   // [D, 2D]
    float* out         = (float*)d_out;           // [B, D]

    g0_semi_part<<<dim3(16, KS0), 256>>>(h, Wi);  // semi partials
    k0b_sum<<<(B * D) / 256, 256>>>();            // g_semi = sum partials
    k1_online<<<dim3(NCHUNK, B), 256>>>(input);   // fused streaming pass
    k2_combine<<<dim3(8, B), 128>>>(h);           // s_tilde | h
    g3_out_part<<<dim3(16, KS3), 256>>>(Wo);      // output GEMM partials
    k4_out<<<(B * D) / 256, 256>>>(out);          // reduce + tanh
}

// round 8
// speedup vs baseline: 1.2586x; 1.0529x over previous
#include <cuda_runtime.h>
#include <math.h>
#include <stdint.h>

#define S 2048
#define B 32
#define D 1024
#define NCHUNK 16
#define CHUNK (S / NCHUNK)   // 128
#define RPW (CHUNK / 8)      // 16 rows per warp
#define STAGES 3
#define KT 64
#define KS0 16               // k-splits for semi GEMM   (k=1024 -> 16 x 64)
#define KS3 32               // k-splits for output GEMM (k=2048 -> 32 x 64)

#define K1_SMEM (8 * STAGES * 256 * 16)   // 8 warps * 3 stages * 4KB = 96 KB

// Static scratch (no allocations allowed). NEVER passed as host-side kernel
// args — always referenced from device code (host-side __device__ symbol
// decay gives an invalid pointer; that was the R4/R5 bug).
__device__ float g_semi[B * D];                    // 128 KB
__device__ float g_p0[(size_t)KS0 * B * D];        // 2 MB
__device__ float g_pm[B * NCHUNK];
__device__ float g_pl[B * NCHUNK];
__device__ float g_pacc[(size_t)B * NCHUNK * D];   // 2 MB
__device__ float g_xcat[B * 2 * D];                // 256 KB (concat(s_tilde, h))
__device__ float g_p3[(size_t)KS3 * B * D];        // 4 MB

// ---------------------------------------------------------------------------
// Shared partial-GEMM body (proven in R2/R6/R7)
// ---------------------------------------------------------------------------
__device__ __forceinline__ void gemm_body(
    const float* __restrict__ A, const float* __restrict__ W,
    float* __restrict__ P, int astride, int wstride)
{
    int jt = blockIdx.x;
    int ks = blockIdx.y;
    int j0 = jt * 64;
    int k0 = ks * KT;

    __shared__ float Xs[32][KT + 1];
    __shared__ float Ws[64][KT + 1];

    int t = threadIdx.x;
    int tb = t & 15;
    int tj = t >> 4;

    for (int i = t; i < 32 * KT; i += 256) {
        int r = i / KT, cc = i % KT;
        Xs[r][cc] = A[(size_t)r * astride + k0 + cc];
    }
    for (int i = t; i < 64 * KT; i += 256) {
        int r = i / KT, cc = i % KT;
        Ws[r][cc] = W[(size_t)(j0 + r) * wstride + k0 + cc];
    }
    __syncthreads();

    float acc[2][4] = {{0.f,0.f,0.f,0.f},{0.f,0.f,0.f,0.f}};
    #pragma unroll 8
    for (int k = 0; k < KT; k++) {
        float x0 = Xs[2 * tb][k];
        float x1 = Xs[2 * tb + 1][k];
        float w0 = Ws[4 * tj + 0][k];
        float w1 = Ws[4 * tj + 1][k];
        float w2 = Ws[4 * tj + 2][k];
        float w3 = Ws[4 * tj + 3][k];
        acc[0][0] += x0 * w0; acc[0][1] += x0 * w1;
        acc[0][2] += x0 * w2; acc[0][3] += x0 * w3;
        acc[1][0] += x1 * w0; acc[1][1] += x1 * w1;
        acc[1][2] += x1 * w2; acc[1][3] += x1 * w3;
    }

    #pragma unroll
    for (int i = 0; i < 2; i++)
        #pragma unroll
        for (int q = 0; q < 4; q++)
            P[((size_t)ks * B + (2 * tb + i)) * D + j0 + 4 * tj + q] = acc[i][q];
}

__global__ void __launch_bounds__(256) g0_semi_part(
    const float* __restrict__ h, const float* __restrict__ Wi)
{
    gemm_body(h, Wi, g_p0, D, D);
}

__global__ void __launch_bounds__(256) g3_out_part(const float* __restrict__ Wo)
{
    gemm_body(g_xcat, Wo, g_p3, 2 * D, 2 * D);
}

__global__ void __launch_bounds__(256) k0b_sum() {
    int i = blockIdx.x * 256 + threadIdx.x;
    float s = 0.f;
    #pragma unroll
    for (int ks = 0; ks < KS0; ks++) s += g_p0[(size_t)ks * B * D + i];
    g_semi[i] = s;
}

// ---------------------------------------------------------------------------
// K1: fused logits + online softmax + weighted accumulation, one HBM pass.
// grid = (NCHUNK, B), 256 thr. Warp-per-row (full D per warp), rows streamed
// through a per-warp 3-deep cp.async smem pipeline. Each lane copies exactly
// the bytes it later reads -> per-thread wait_group suffices, no hot syncs.
// ---------------------------------------------------------------------------
__global__ void __launch_bounds__(256, 2) k1_online(const float* __restrict__ input) {
    extern __shared__ float4 stg[];              // 8 * STAGES * 256 float4
    int c = blockIdx.x, b = blockIdx.y;
    int t = threadIdx.x, warp = t >> 5, lane = t & 31;

    float4 sem[8];
    const float4* semi4 = (const float4*)(g_semi + b * D);
    #pragma unroll
    for (int j = 0; j < 8; j++) sem[j] = semi4[lane + 32 * j];

    float4* wst = stg + warp * (STAGES * 256);
    int s0 = c * CHUNK + warp * RPW;
    const float4* base = (const float4*)(input + ((size_t)s0 * B + b) * D);
    const size_t rstride = (size_t)B * D / 4;    // float4 step for s+1

    // prologue: stage rows 0..STAGES-1
    #pragma unroll
    for (int k = 0; k < STAGES; k++) {
        const float4* src = base + (size_t)k * rstride;
        float4* dst = wst + k * 256;
        #pragma unroll
        for (int j = 0; j < 8; j++) {
            uint32_t sa = (uint32_t)__cvta_generic_to_shared(dst + lane + 32 * j);
            asm volatile("cp.async.cg.shared.global [%0], [%1], 16;"
                         :: "r"(sa), "l"(src + lane + 32 * j));
        }
        asm volatile("cp.async.commit_group;");
    }

    float4 acc[8];
    #pragma unroll
    for (int j = 0; j < 8; j++) acc[j] = make_float4(0.f, 0.f, 0.f, 0.f);
    float m = -INFINITY, l = 0.f;

    for (int i = 0; i < RPW; i++) {
        asm volatile("cp.async.wait_group %0;" :: "n"(STAGES - 1));
        float4* cur = wst + (i % STAGES) * 256;
        float4 x[8];
        #pragma unroll
        for (int j = 0; j < 8; j++) x[j] = cur[lane + 32 * j];

        // refill this stage with row i+STAGES (after x is in registers)
        if (i + STAGES < RPW) {
            const float4* src = base + (size_t)(i + STAGES) * rstride;
            #pragma unroll
            for (int j = 0; j < 8; j++) {
                uint32_t sa = (uint32_t)__cvta_generic_to_shared(cur + lane + 32 * j);
                asm volatile("cp.async.cg.shared.global [%0], [%1], 16;"
                             :: "r"(sa), "l"(src + lane + 32 * j));
            }
        }
        asm volatile("cp.async.commit_group;");

        float p = 0.f;
        #pragma unroll
        for (int j = 0; j < 8; j++)
            p += x[j].x * sem[j].x + x[j].y * sem[j].y
               + x[j].z * sem[j].z + x[j].w * sem[j].w;
        #pragma unroll
        for (int o = 16; o; o >>= 1) p += __shfl_xor_sync(0xffffffffu, p, o);
        if (p > m) {
            float sc = __expf(m - p);            // exp(-inf)=0 handles first row
            #pragma unroll
            for (int j = 0; j < 8; j++) {
                acc[j].x *= sc; acc[j].y *= sc; acc[j].z *= sc; acc[j].w *= sc;
            }
            l *= sc; m = p;
        }
        float w = __expf(p - m);
        l += w;
        #pragma unroll
        for (int j = 0; j < 8; j++) {
            acc[j].x += w * x[j].x; acc[j].y += w * x[j].y;
            acc[j].z += w * x[j].z; acc[j].w += w * x[j].w;
        }
    }

    // merge 8 warps; reuse stage smem as the merge buffer
    __shared__ float sm[8], sl[8];
    if (lane == 0) { sm[warp] = m; sl[warp] = l; }
    asm volatile("cp.async.wait_group 0;");
    __syncthreads();                             // quiesce stages + publish sm/sl

    float M = -INFINITY;
    #pragma unroll
    for (int w = 0; w < 8; w++) M = fmaxf(M, sm[w]);
    float L = 0.f;
    #pragma unroll
    for (int w = 0; w < 8; w++) L += sl[w] * __expf(sm[w] - M);
    float f = __expf(m - M);

    float4* sacc = stg;                          // 8 * 256 float4 = 32 KB
    #pragma unroll
    for (int j = 0; j < 8; j++) {
        float4 a = acc[j];
        a.x *= f; a.y *= f; a.z *= f; a.w *= f;
        sacc[warp * 256 + lane + 32 * j] = a;
    }
    __syncthreads();
    float4 s = make_float4(0.f, 0.f, 0.f, 0.f);
    #pragma unroll
    for (int w = 0; w < 8; w++) {
        float4 a = sacc[w * 256 + t];
        s.x += a.x; s.y += a.y; s.z += a.z; s.w += a.w;
    }
    ((float4*)(g_pacc + (size_t)(b * NCHUNK + c) * D))[t] = s;
    if (t == 0) { g_pm[b * NCHUNK + c] = M; g_pl[b * NCHUNK + c] = L; }
}

// ---------------------------------------------------------------------------
// K2: combine chunk partials -> s_tilde, build xcat = [s_tilde | h]
// grid = (4 d-slices, B), 256 threads. No fv[] array (avoids local spill);
// exp recomputed from smem-cached pm (MUFU is cheap).
// ---------------------------------------------------------------------------
__global__ void __launch_bounds__(256) k2_combine(const float* __restrict__ h) {
    __shared__ float spm[NCHUNK], spl[NCHUNK];
    int b = blockIdx.y;
    int t = threadIdx.x;
    int d = blockIdx.x * 256 + t;
    if (t < NCHUNK) { spm[t] = g_pm[b * NCHUNK + t]; spl[t] = g_pl[b * NCHUNK + t]; }
    __syncthreads();

    float M = -INFINITY;
    #pragma unroll
    for (int c = 0; c < NCHUNK; c++) M = fmaxf(M, spm[c]);
    float L = 0.f;
    #pragma unroll
    for (int c = 0; c < NCHUNK; c++) L += spl[c] * __expf(spm[c] - M);
    float invL = 1.f / L;

    float s = 0.f;
    #pragma unroll
    for (int c = 0; c < NCHUNK; c++)
        s += g_pacc[(size_t)(b * NCHUNK + c) * D + d] * __expf(spm[c] - M);

    g_xcat[(size_t)b * 2 * D + d]     = s * invL;
    g_xcat[(size_t)b * 2 * D + D + d] = h[(size_t)b * D + d];
}

// ---------------------------------------------------------------------------
// K4: reduce split-K partials + tanh -> output [B, D]
// ---------------------------------------------------------------------------
__global__ void __launch_bounds__(256) k4_out(float* __restrict__ out) {
    int i = blockIdx.x * 256 + threadIdx.x;
    float s = 0.f;
    #pragma unroll
    for (int ks = 0; ks < KS3; ks++) s += g_p3[(size_t)ks * B * D + i];
    out[i] = tanhf(s);
}

// ---------------------------------------------------------------------------
extern "C" void kernel_launch(void* const* d_in, const int* in_sizes, int n_in,
                              void* d_out, int out_size) {
    const float* input = (const float*)d_in[0];   // [S, B, D]
    const float* h     = (const float*)d_in[1];   // [B, D]
    const float* Wi    = (const float*)d_in[2];   // [D, D]
    const float* Wo    = (const float*)d_in[3];   // [D, 2D]
    float* out         = (float*)d_out;           // [B, D]

    cudaFuncSetAttribute(k1_online, cudaFuncAttributeMaxDynamicSharedMemorySize,
                         K1_SMEM);

    g0_semi_part<<<dim3(16, KS0), 256>>>(h, Wi);         // semi partials
    k0b_sum<<<(B * D) / 256, 256>>>();                   // g_semi = sum partials
    k1_online<<<dim3(NCHUNK, B), 256, K1_SMEM>>>(input); // fused streaming pass
    k2_combine<<<dim3(4, B), 256>>>(h);                  // s_tilde | h
    g3_out_part<<<dim3(16, KS3), 256>>>(Wo);             // output GEMM partials
    k4_out<<<(B * D) / 256, 256>>>(out);                 // reduce + tanh
}